// round 13
// baseline (speedup 1.0000x reference)
#include <cuda_runtime.h>
#include <cuda_bf16.h>
#include <cstdint>

// Activations/weights stored as bf16x2 k-pair words [loc][kp][batch] (batch innermost).
// Zero-init (bss) of unwritten pad rows is guaranteed; pad weights are explicit zeros.
__device__ uint32_t g_P0[400 * 32 * 4096];    // im2col, K'=64 padded (kp=32)
__device__ uint32_t g_H0[400 * 16 * 4096];    // l0 out, 32 couts -> 16 pairs
__device__ uint32_t g_H1[100 * 32 * 4096];    // l1 out, 64 couts -> 32 pairs
__device__ float    g_PART[4 * 4 * 128 * 4096]; // l2 split-K partials (fp32)
__device__ uint32_t g_W0c[400 * 32 * 32];     // [loc][co][kp], permuted + padded
__device__ uint32_t g_W1c[100 * 64 * 64];
__device__ uint32_t g_W2c[4 * 128 * 800];

static __device__ __forceinline__ float tanhap(float x) {
    float y; asm("tanh.approx.f32 %0, %1;" : "=f"(y) : "f"(x)); return y;
}
static __device__ __forceinline__ uint32_t packbf(float lo, float hi) {
    uint32_t r; asm("cvt.rn.bf16x2.f32 %0, %1, %2;" : "=r"(r) : "f"(hi), "f"(lo)); return r;
}
static __device__ __forceinline__ void mma_bf16(float* d, uint32_t a0, uint32_t a1,
                                                uint32_t a2, uint32_t a3,
                                                uint32_t b0, uint32_t b1) {
    asm volatile(
        "mma.sync.aligned.m16n8k16.row.col.f32.bf16.bf16.f32 "
        "{%0,%1,%2,%3}, {%4,%5,%6,%7}, {%8,%9}, {%0,%1,%2,%3};"
        : "+f"(d[0]), "+f"(d[1]), "+f"(d[2]), "+f"(d[3])
        : "r"(a0), "r"(a1), "r"(a2), "r"(a3), "r"(b0), "r"(b1));
}
static __device__ __forceinline__ void cpa16(void* s, const void* g) {
    uint32_t sa = (uint32_t)__cvta_generic_to_shared(s);
    asm volatile("cp.async.ca.shared.global [%0], [%1], 16;" :: "r"(sa), "l"(g));
}
static __device__ __forceinline__ void cpa_commit() {
    asm volatile("cp.async.commit_group;");
}
static __device__ __forceinline__ void cpa_wait_all() {
    asm volatile("cp.async.wait_group 0;");
}

// ---------------------------------------------------------------------------
// Weight pre-conversion to bf16x2 pair-packed, layer-specific k' permutation.
// L0: k' = c*10 + (dh*3+dw), slots q=9 and kp>=30 are zero pad. kp = c*5+m.
// ---------------------------------------------------------------------------
__global__ void __launch_bounds__(256) wconv0_k(const float* __restrict__ W0) {
    int idx = blockIdx.x * 256 + threadIdx.x;        // over 400*32*32
    if (idx >= 400 * 32 * 32) return;
    int kp = idx & 31, row = idx >> 5;               // row = loc*32+co
    uint32_t w = 0;
    if (kp < 30) {
        int c = kp / 5, m = kp - c * 5;
        int q0 = 2 * m, q1 = 2 * m + 1;
        float f0 = W0[row * 54 + c * 9 + q0];
        float f1 = (q1 < 9) ? W0[row * 54 + c * 9 + q1] : 0.0f;
        w = packbf(f0, f1);
    }
    g_W0c[idx] = w;
}
// L1: k' = r*32 + cin (r = dh*2+dw). kp = r*16 + cp.
__global__ void __launch_bounds__(256) wconv1_k(const float* __restrict__ W1) {
    int idx = blockIdx.x * 256 + threadIdx.x;        // over 100*64*64
    if (idx >= 100 * 64 * 64) return;
    int kp = idx & 63, row = idx >> 6;               // row = loc*64+co
    int r = kp >> 4, cp = kp & 15;
    const float* base = W1 + (size_t)row * 128;
    g_W1c[idx] = packbf(base[(2 * cp) * 4 + r], base[(2 * cp + 1) * 4 + r]);
}
// L2: k' = r*64 + cin (r = dh*5+dw). kp = r*32 + cp.
__global__ void __launch_bounds__(256) wconv2_k(const float* __restrict__ W2) {
    int idx = blockIdx.x * 256 + threadIdx.x;        // over 4*128*800
    if (idx >= 4 * 128 * 800) return;
    int kp = idx % 800, row = idx / 800;             // row = loc*128+co
    int r = kp >> 5, cp = kp & 31;
    const float* base = W2 + (size_t)row * 1600;
    g_W2c[idx] = packbf(base[(2 * cp) * 25 + r], base[(2 * cp + 1) * 25 + r]);
}

// ---------------------------------------------------------------------------
// im2col: x[B,6,60,60] -> g_P0[loc][kp][B] bf16x2 pair-packed.
// Block = (c, i) x 64 batches: loads 3 h-rows fully (all k-pairs block-local).
// kp = c*5 + m; word m = {q=2m, q=2m+1} with q = dh*3+dw (m=4 pairs with pad).
// ---------------------------------------------------------------------------
__global__ void __launch_bounds__(256) im2col_k(const float* __restrict__ x) {
    const int ci = blockIdx.x;          // 0..119
    const int c = ci / 20, i = ci % 20;
    const int b0 = blockIdx.y * 64;
    constexpr int P = 65;
    __shared__ float s[3 * 60 * P];     // [dh*60 + w][bl]

    // Read: 3 rows x 64 batches x 15 float4, coalesced; scalar scatter (~2-way)
    const float* src = x + c * 3600 + (3 * i) * 60;
    for (int e = threadIdx.x; e < 3 * 64 * 15; e += 256) {
        int dh = e / 960, rem = e - dh * 960;
        int bl = rem / 15, w4 = rem - bl * 15;
        float4 v = *(const float4*)(src + (size_t)(b0 + bl) * 21600 + dh * 60 + 4 * w4);
        float* d = &s[(dh * 60 + 4 * w4) * P + bl];
        d[0] = v.x; d[P] = v.y; d[2 * P] = v.z; d[3 * P] = v.w;
    }
    __syncthreads();

    // Write: per (j, m, bl4): gather pair values (conflict-free), pack, STG.128
    for (int e = threadIdx.x; e < 20 * 5 * 16; e += 256) {
        int bl4 = e & 15, jm = e >> 4;
        int j = jm / 5, m = jm - j * 5;
        int q0 = 2 * m;
        int dh0 = q0 / 3, dw0 = q0 - 3 * dh0;
        bool has1 = (m < 4);
        int q1 = q0 + 1;
        int dh1 = q1 / 3, dw1 = q1 - 3 * dh1;
        const float* s0 = &s[(dh0 * 60 + 3 * j + dw0) * P + 4 * bl4];
        const float* s1 = &s[(dh1 * 60 + 3 * j + dw1) * P + 4 * bl4];
        uint32_t w[4];
#pragma unroll
        for (int t = 0; t < 4; t++)
            w[t] = packbf(s0[t], has1 ? s1[t] : 0.0f);
        *(uint4*)&g_P0[((size_t)(i * 20 + j) * 32 + c * 5 + m) * 4096 + b0 + 4 * bl4] =
            make_uint4(w[0], w[1], w[2], w[3]);
    }
}

// ---------------------------------------------------------------------------
// Locally-connected GEMM on bf16 tensor cores (mma.sync m16n8k16).
// 256 threads = 8 warps. CTA tile: BB batches x COUT_BLK couts.
// smem elems are bf16x2 k-pair words; inner loop = pure LDS + MMA.
// MODE: A-row mapping (0: l0 direct, 1: l1, 2: l2). KTOT/KCHUNK in kp units.
// ---------------------------------------------------------------------------
template <int MODE, int WOUT, int COUT, int COUT_BLK, int KCHUNK, int BB,
          int KSPLIT, bool PARTIAL, long long KZSTRIDE, int KTOT, int STAGES>
static __device__ __forceinline__ void lc_mma_body(const uint32_t* __restrict__ in,
                                                   const uint32_t* __restrict__ W,
                                                   const float* __restrict__ bias,
                                                   void* __restrict__ outp) {
    constexpr int KPER   = KTOT / KSPLIT;
    constexpr int NCHUNK = KPER / KCHUNK;
    constexpr int AS     = BB + 8;           // A smem stride (words, == 8 mod 32)
    constexpr int WS     = KCHUNK + 4;       // W smem stride
    constexpr int NCOT   = COUT_BLK / 16;
    constexpr int B      = 4096;

    extern __shared__ __align__(16) uint32_t dsm[];
    uint32_t* Asm = dsm;                         // [STAGES][KCHUNK][AS]
    uint32_t* Wsm = dsm + STAGES * KCHUNK * AS;  // [STAGES][COUT_BLK][WS]

    const int loc = blockIdx.x;
    const int i = loc / WOUT, j = loc - i * WOUT;
    const int b0 = blockIdx.y * BB;
    const int cz = (blockIdx.z / KSPLIT) * COUT_BLK;
    const int kz = blockIdx.z % KSPLIT;
    const int t = threadIdx.x;
    const int lane = t & 31;
    const int wid = t >> 5;
    const int qr = lane >> 2, qc = lane & 3;
    const int cot = wid % NCOT;
    const int bg  = wid / NCOT;

    const uint32_t* Wl = W + ((size_t)loc * COUT + cz) * KTOT;
    const int kbeg = kz * KPER;

    auto load_stage = [&](int st, int kp0) {
        uint32_t* As = Asm + st * KCHUNK * AS;
        uint32_t* Ws = Wsm + st * COUT_BLK * WS;
        for (int id = t; id < KCHUNK * BB / 4; id += 256) {
            int kc = id / (BB / 4), off = (id % (BB / 4)) * 4;
            int kp = kp0 + kc;
            int row;
            if (MODE == 0) {
                row = loc * 32 + kp;
            } else if (MODE == 1) {
                int r = kp >> 4, cp = kp & 15;
                int loc_in = (2 * i + (r >> 1)) * 20 + 2 * j + (r & 1);
                row = loc_in * 16 + cp;
            } else {
                int r = kp >> 5, cp = kp & 31;
                int dh = r / 5, dw = r - 5 * dh;
                int loc_in = (5 * i + dh) * 10 + 5 * j + dw;
                row = loc_in * 32 + cp;
            }
            cpa16(&As[kc * AS + off], in + (size_t)row * B + b0 + off);
        }
        for (int id = t; id < COUT_BLK * KCHUNK / 4; id += 256) {
            int co = id / (KCHUNK / 4), off = (id % (KCHUNK / 4)) * 4;
            cpa16(&Ws[co * WS + off], Wl + (size_t)co * KTOT + kp0 + off);
        }
        cpa_commit();
    };

    float acc[8][4];
#pragma unroll
    for (int nt = 0; nt < 8; nt++)
#pragma unroll
        for (int r = 0; r < 4; r++) acc[nt][r] = 0.0f;

    load_stage(0, kbeg);
    for (int ch = 0; ch < NCHUNK; ch++) {
        cpa_wait_all();
        __syncthreads();
        if (STAGES == 2 && ch + 1 < NCHUNK)
            load_stage((ch + 1) & 1, kbeg + (ch + 1) * KCHUNK);

        const int st = (STAGES == 2) ? (ch & 1) : 0;
        const uint32_t* As = Asm + st * KCHUNK * AS;
        const uint32_t* Ws = Wsm + st * COUT_BLK * WS;

#pragma unroll
        for (int kk = 0; kk < KCHUNK; kk += 8) {   // 8 kp words = k16 step
            uint32_t a0 = Ws[(cot * 16 + qr) * WS + kk + qc];
            uint32_t a1 = Ws[(cot * 16 + qr + 8) * WS + kk + qc];
            uint32_t a2 = Ws[(cot * 16 + qr) * WS + kk + qc + 4];
            uint32_t a3 = Ws[(cot * 16 + qr + 8) * WS + kk + qc + 4];
#pragma unroll
            for (int p = 0; p < 4; p++) {
                int ab = bg * 64 + p * 16 + 2 * qr;
                uint2 v0 = *(const uint2*)&As[(kk + qc) * AS + ab];
                uint2 v1 = *(const uint2*)&As[(kk + qc + 4) * AS + ab];
                mma_bf16(acc[p * 2 + 0], a0, a1, a2, a3, v0.x, v1.x);
                mma_bf16(acc[p * 2 + 1], a0, a1, a2, a3, v0.y, v1.y);
            }
        }
        if (STAGES == 1) break;
    }

    // Epilogue: stage fp32 D to smem, then coalesced global writes.
    __syncthreads();
    constexpr int DS = BB + 8;
    float* Dsm = (float*)dsm;
#pragma unroll
    for (int p = 0; p < 4; p++) {
        int base = bg * 64 + p * 16 + 4 * qc;
        int row0 = cot * 16 + qr;
        *(float4*)&Dsm[row0 * DS + base] =
            make_float4(acc[2 * p][0], acc[2 * p + 1][0], acc[2 * p][1], acc[2 * p + 1][1]);
        *(float4*)&Dsm[(row0 + 8) * DS + base] =
            make_float4(acc[2 * p][2], acc[2 * p + 1][2], acc[2 * p][3], acc[2 * p + 1][3]);
    }
    __syncthreads();

    if (PARTIAL) {
        float* ob = (float*)outp + (size_t)kz * KZSTRIDE;
        for (int idx = t; idx < COUT_BLK * BB; idx += 256) {
            int co = idx / BB, bl = idx - co * BB;
            ob[((size_t)loc * COUT + cz + co) * B + b0 + bl] = Dsm[co * DS + bl];
        }
    } else {
        uint32_t* ob = (uint32_t*)outp;
        for (int idx = t; idx < (COUT_BLK / 2) * BB; idx += 256) {
            int cop = idx / BB, bl = idx - cop * BB;
            float d0 = tanhap(Dsm[(2 * cop) * DS + bl] +
                              bias[(size_t)loc * COUT + cz + 2 * cop]);
            float d1 = tanhap(Dsm[(2 * cop + 1) * DS + bl] +
                              bias[(size_t)loc * COUT + cz + 2 * cop + 1]);
            ob[((size_t)loc * (COUT / 2) + (cz >> 1) + cop) * B + b0 + bl] =
                packbf(d0, d1);
        }
    }
}

// L0: KTOT=32 kp (K'=64 padded), 1 chunk, BB=256, COUT_BLK=32.
__global__ void __launch_bounds__(256) k_l0(const float* __restrict__ b) {
    lc_mma_body<0, 20, 32, 32, 32, 256, 1, false, 0, 32, 1>(g_P0, g_W0c, b, g_H0);
}
// L1: KTOT=64 kp, KCHUNK=32, 2 chunks, 2-stage, BB=128, COUT_BLK=64.
__global__ void __launch_bounds__(256) k_l1(const float* __restrict__ b) {
    lc_mma_body<1, 10, 64, 64, 32, 128, 1, false, 0, 64, 2>(g_H0, g_W1c, b, g_H1);
}
// L2: KTOT=800 kp, split-K=4 (200 kp), KCHUNK=40, 5 chunks, 2-stage. Partials.
__global__ void __launch_bounds__(256) k_l2(const float* __restrict__ b) {
    lc_mma_body<2, 2, 128, 64, 40, 128, 4, true, 4LL * 128 * 4096, 800, 2>(
        g_H1, g_W2c, b, g_PART);
}

// ---------------------------------------------------------------------------
// Classifier + softmax with l2 split-K combine FUSED (bias + tanh inline).
// 128 blocks x 256 threads: 32 batches x 8 f-groups.
// flatten f = c*4 + loc2; partial row = loc2*128 + c = (f&3)*128 + (f>>2).
// ---------------------------------------------------------------------------
__global__ void __launch_bounds__(256) classifier_k(const float* __restrict__ info,
                                                    const float* __restrict__ Wc,
                                                    const float* __restrict__ bc,
                                                    const float* __restrict__ B2,
                                                    float* __restrict__ out) {
    constexpr int ST = 4 * 128 * 4096;
    __shared__ float wsm[1030];
    __shared__ float bsm[512];
    __shared__ float red[8][32][2];
    for (int e = threadIdx.x; e < 1028; e += 256) wsm[e] = Wc[e];
    if (threadIdx.x < 2) wsm[1028 + threadIdx.x] = bc[threadIdx.x];
    for (int e = threadIdx.x; e < 512; e += 256) bsm[e] = B2[e];
    __syncthreads();

    const int fg = threadIdx.x >> 5, lane = threadIdx.x & 31;
    const int b = blockIdx.x * 32 + lane;
    float l0 = 0.f, l1 = 0.f;
#pragma unroll 4
    for (int ff = 0; ff < 64; ff++) {
        int f = fg * 64 + ff;
        int row = (f & 3) * 128 + (f >> 2);
        size_t base = (size_t)row * 4096 + b;
        float s = bsm[row] + g_PART[base] + g_PART[base + ST]
                + g_PART[base + 2 * ST] + g_PART[base + 3 * ST];
        float hv = tanhap(s);
        l0 += hv * wsm[f * 2];
        l1 += hv * wsm[f * 2 + 1];
    }
    red[fg][lane][0] = l0;
    red[fg][lane][1] = l1;
    __syncthreads();

    if (threadIdx.x < 32) {
        int bb = blockIdx.x * 32 + threadIdx.x;
        float s0 = wsm[1028], s1 = wsm[1029];
#pragma unroll
        for (int g = 0; g < 8; g++) { s0 += red[g][threadIdx.x][0]; s1 += red[g][threadIdx.x][1]; }
        float i0 = info[2 * bb], i1 = info[2 * bb + 1];
        s0 += i0 * wsm[512 * 2]     + i1 * wsm[513 * 2];
        s1 += i0 * wsm[512 * 2 + 1] + i1 * wsm[513 * 2 + 1];
        float m = fmaxf(s0, s1);
        float e0 = __expf(s0 - m), e1 = __expf(s1 - m);
        float inv = 1.0f / (e0 + e1);
        ((float2*)out)[bb] = make_float2(e0 * inv, e1 * inv);
    }
}

extern "C" void kernel_launch(void* const* d_in, const int* in_sizes, int n_in,
                              void* d_out, int out_size) {
    const float* x    = (const float*)d_in[0];
    const float* info = (const float*)d_in[1];
    const float* W0   = (const float*)d_in[2];
    const float* B0   = (const float*)d_in[3];
    const float* W1   = (const float*)d_in[4];
    const float* B1   = (const float*)d_in[5];
    const float* W2   = (const float*)d_in[6];
    const float* B2   = (const float*)d_in[7];
    const float* Wc   = (const float*)d_in[8];
    const float* bc   = (const float*)d_in[9];
    float* out = (float*)d_out;

    // Dynamic smem: STAGES*(KCHUNK*AS + COUT_BLK*WS) words (4B each)
    const int s_l0 = (32 * 264 + 32 * 36) * 4;              // 38400
    const int s_l1 = 2 * (32 * 136 + 64 * 36) * 4;          // 53248
    const int s_l2 = 2 * (40 * 136 + 64 * 44) * 4;          // 66048
    cudaFuncSetAttribute(k_l0, cudaFuncAttributeMaxDynamicSharedMemorySize, s_l0);
    cudaFuncSetAttribute(k_l1, cudaFuncAttributeMaxDynamicSharedMemorySize, s_l1);
    cudaFuncSetAttribute(k_l2, cudaFuncAttributeMaxDynamicSharedMemorySize, s_l2);

    wconv0_k<<<(400 * 32 * 32 + 255) / 256, 256>>>(W0);
    wconv1_k<<<(100 * 64 * 64 + 255) / 256, 256>>>(W1);
    wconv2_k<<<(4 * 128 * 800 + 255) / 256, 256>>>(W2);
    im2col_k<<<dim3(120, 64), 256>>>(x);
    k_l0<<<dim3(400, 16, 1), 256, s_l0>>>(B0);        // 6400 CTAs
    k_l1<<<dim3(100, 32, 1), 256, s_l1>>>(B1);        // 3200 CTAs
    k_l2<<<dim3(4, 32, 8), 256, s_l2>>>(B2);          // 1024 CTAs (2 co x 4 kz)
    classifier_k<<<128, 256>>>(info, Wc, bc, B2, out);
}

// round 14
// speedup vs baseline: 1.1130x; 1.1130x over previous
#include <cuda_runtime.h>
#include <cuda_bf16.h>
#include <cstdint>

// Activations/weights stored as bf16x2 k-pair words [loc][kp][batch] (batch innermost).
// Zero-init (bss) of unwritten pad rows is guaranteed; pad weights are explicit zeros.
__device__ uint32_t g_P0[400 * 32 * 4096];    // im2col, K'=64 padded (kp=32)
__device__ uint32_t g_H0[400 * 16 * 4096];    // l0 out, 32 couts -> 16 pairs
__device__ uint32_t g_H1[100 * 32 * 4096];    // l1 out, 64 couts -> 32 pairs
__device__ float    g_PART[4 * 4 * 128 * 4096]; // l2 split-K partials (fp32)
__device__ uint32_t g_W0c[400 * 32 * 32];     // [loc][co][kp], permuted + padded
__device__ uint32_t g_W1c[100 * 64 * 64];
__device__ uint32_t g_W2c[4 * 128 * 800];

static __device__ __forceinline__ float tanhap(float x) {
    float y; asm("tanh.approx.f32 %0, %1;" : "=f"(y) : "f"(x)); return y;
}
static __device__ __forceinline__ uint32_t packbf(float lo, float hi) {
    uint32_t r; asm("cvt.rn.bf16x2.f32 %0, %1, %2;" : "=r"(r) : "f"(hi), "f"(lo)); return r;
}
static __device__ __forceinline__ void mma_bf16(float* d, uint32_t a0, uint32_t a1,
                                                uint32_t a2, uint32_t a3,
                                                uint32_t b0, uint32_t b1) {
    asm volatile(
        "mma.sync.aligned.m16n8k16.row.col.f32.bf16.bf16.f32 "
        "{%0,%1,%2,%3}, {%4,%5,%6,%7}, {%8,%9}, {%0,%1,%2,%3};"
        : "+f"(d[0]), "+f"(d[1]), "+f"(d[2]), "+f"(d[3])
        : "r"(a0), "r"(a1), "r"(a2), "r"(a3), "r"(b0), "r"(b1));
}
static __device__ __forceinline__ void cpa16(void* s, const void* g) {
    uint32_t sa = (uint32_t)__cvta_generic_to_shared(s);
    asm volatile("cp.async.ca.shared.global [%0], [%1], 16;" :: "r"(sa), "l"(g));
}
static __device__ __forceinline__ void cpa_commit() {
    asm volatile("cp.async.commit_group;");
}
static __device__ __forceinline__ void cpa_wait_all() {
    asm volatile("cp.async.wait_group 0;");
}

// ---------------------------------------------------------------------------
// Weight pre-conversion to bf16x2 pair-packed, layer-specific k' permutation.
// L0: k' = c*10 + (dh*3+dw), slots q=9 and kp>=30 are zero pad. kp = c*5+m.
// ---------------------------------------------------------------------------
__global__ void __launch_bounds__(256) wconv0_k(const float* __restrict__ W0) {
    int idx = blockIdx.x * 256 + threadIdx.x;        // over 400*32*32
    if (idx >= 400 * 32 * 32) return;
    int kp = idx & 31, row = idx >> 5;               // row = loc*32+co
    uint32_t w = 0;
    if (kp < 30) {
        int c = kp / 5, m = kp - c * 5;
        int q0 = 2 * m, q1 = 2 * m + 1;
        float f0 = W0[row * 54 + c * 9 + q0];
        float f1 = (q1 < 9) ? W0[row * 54 + c * 9 + q1] : 0.0f;
        w = packbf(f0, f1);
    }
    g_W0c[idx] = w;
}
// L1: k' = r*32 + cin (r = dh*2+dw). kp = r*16 + cp.
__global__ void __launch_bounds__(256) wconv1_k(const float* __restrict__ W1) {
    int idx = blockIdx.x * 256 + threadIdx.x;        // over 100*64*64
    if (idx >= 100 * 64 * 64) return;
    int kp = idx & 63, row = idx >> 6;               // row = loc*64+co
    int r = kp >> 4, cp = kp & 15;
    const float* base = W1 + (size_t)row * 128;
    g_W1c[idx] = packbf(base[(2 * cp) * 4 + r], base[(2 * cp + 1) * 4 + r]);
}
// L2: k' = r*64 + cin (r = dh*5+dw). kp = r*32 + cp.
__global__ void __launch_bounds__(256) wconv2_k(const float* __restrict__ W2) {
    int idx = blockIdx.x * 256 + threadIdx.x;        // over 4*128*800
    if (idx >= 4 * 128 * 800) return;
    int kp = idx % 800, row = idx / 800;             // row = loc*128+co
    int r = kp >> 5, cp = kp & 31;
    const float* base = W2 + (size_t)row * 1600;
    g_W2c[idx] = packbf(base[(2 * cp) * 25 + r], base[(2 * cp + 1) * 25 + r]);
}

// ---------------------------------------------------------------------------
// im2col: x[B,6,60,60] -> g_P0[loc][kp][B] bf16x2 pair-packed.
// Block = (c, i) x 32 batches (smem 23.8KB -> 8 CTAs/SM). Loads 3 h-rows fully
// (all k-pairs block-local). kp = c*5 + m; word m = {q=2m, q=2m+1}, q=dh*3+dw.
// ---------------------------------------------------------------------------
__global__ void __launch_bounds__(256) im2col_k(const float* __restrict__ x) {
    const int ci = blockIdx.x;          // 0..119
    const int c = ci / 20, i = ci % 20;
    const int b0 = blockIdx.y * 32;
    constexpr int P = 33;
    __shared__ float s[3 * 60 * P];     // [dh*60 + w][bl]

    // Read: 3 rows x 32 batches x 15 float4, coalesced; scalar scatter (~2-way)
    const float* src = x + c * 3600 + (3 * i) * 60;
    for (int e = threadIdx.x; e < 3 * 32 * 15; e += 256) {
        int dh = e / 480, rem = e - dh * 480;
        int bl = rem / 15, w4 = rem - bl * 15;
        float4 v = *(const float4*)(src + (size_t)(b0 + bl) * 21600 + dh * 60 + 4 * w4);
        float* d = &s[(dh * 60 + 4 * w4) * P + bl];
        d[0] = v.x; d[P] = v.y; d[2 * P] = v.z; d[3 * P] = v.w;
    }
    __syncthreads();

    // Write: per (j, m, bl4): gather pair values, pack, STG.128
    for (int e = threadIdx.x; e < 20 * 5 * 8; e += 256) {
        int bl4 = e & 7, jm = e >> 3;
        int j = jm / 5, m = jm - j * 5;
        int q0 = 2 * m;
        int dh0 = q0 / 3, dw0 = q0 - 3 * dh0;
        bool has1 = (m < 4);
        int q1 = q0 + 1;
        int dh1 = q1 / 3, dw1 = q1 - 3 * dh1;
        const float* s0 = &s[(dh0 * 60 + 3 * j + dw0) * P + 4 * bl4];
        const float* s1 = &s[(dh1 * 60 + 3 * j + dw1) * P + 4 * bl4];
        uint32_t w[4];
#pragma unroll
        for (int t = 0; t < 4; t++)
            w[t] = packbf(s0[t], has1 ? s1[t] : 0.0f);
        *(uint4*)&g_P0[((size_t)(i * 20 + j) * 32 + c * 5 + m) * 4096 + b0 + 4 * bl4] =
            make_uint4(w[0], w[1], w[2], w[3]);
    }
}

// ---------------------------------------------------------------------------
// Locally-connected GEMM on bf16 tensor cores (mma.sync m16n8k16).
// 256 threads = 8 warps. CTA tile: BB batches x COUT_BLK couts.
// smem elems are bf16x2 k-pair words; inner loop = pure LDS + MMA.
// MODE: A-row mapping (0: l0 direct, 1: l1, 2: l2). KTOT/KCHUNK in kp units.
// ---------------------------------------------------------------------------
template <int MODE, int WOUT, int COUT, int COUT_BLK, int KCHUNK, int BB,
          int KSPLIT, bool PARTIAL, long long KZSTRIDE, int KTOT, int STAGES>
static __device__ __forceinline__ void lc_mma_body(const uint32_t* __restrict__ in,
                                                   const uint32_t* __restrict__ W,
                                                   const float* __restrict__ bias,
                                                   void* __restrict__ outp) {
    constexpr int KPER   = KTOT / KSPLIT;
    constexpr int NCHUNK = KPER / KCHUNK;
    constexpr int AS     = BB + 8;           // A smem stride (words, == 8 mod 32)
    constexpr int WS     = KCHUNK + 4;       // W smem stride
    constexpr int NCOT   = COUT_BLK / 16;
    constexpr int B      = 4096;

    extern __shared__ __align__(16) uint32_t dsm[];
    uint32_t* Asm = dsm;                         // [STAGES][KCHUNK][AS]
    uint32_t* Wsm = dsm + STAGES * KCHUNK * AS;  // [STAGES][COUT_BLK][WS]

    const int loc = blockIdx.x;
    const int i = loc / WOUT, j = loc - i * WOUT;
    const int b0 = blockIdx.y * BB;
    const int cz = (blockIdx.z / KSPLIT) * COUT_BLK;
    const int kz = blockIdx.z % KSPLIT;
    const int t = threadIdx.x;
    const int lane = t & 31;
    const int wid = t >> 5;
    const int qr = lane >> 2, qc = lane & 3;
    const int cot = wid % NCOT;
    const int bg  = wid / NCOT;

    const uint32_t* Wl = W + ((size_t)loc * COUT + cz) * KTOT;
    const int kbeg = kz * KPER;

    auto load_stage = [&](int st, int kp0) {
        uint32_t* As = Asm + st * KCHUNK * AS;
        uint32_t* Ws = Wsm + st * COUT_BLK * WS;
        for (int id = t; id < KCHUNK * BB / 4; id += 256) {
            int kc = id / (BB / 4), off = (id % (BB / 4)) * 4;
            int kp = kp0 + kc;
            int row;
            if (MODE == 0) {
                row = loc * 32 + kp;
            } else if (MODE == 1) {
                int r = kp >> 4, cp = kp & 15;
                int loc_in = (2 * i + (r >> 1)) * 20 + 2 * j + (r & 1);
                row = loc_in * 16 + cp;
            } else {
                int r = kp >> 5, cp = kp & 31;
                int dh = r / 5, dw = r - 5 * dh;
                int loc_in = (5 * i + dh) * 10 + 5 * j + dw;
                row = loc_in * 32 + cp;
            }
            cpa16(&As[kc * AS + off], in + (size_t)row * B + b0 + off);
        }
        for (int id = t; id < COUT_BLK * KCHUNK / 4; id += 256) {
            int co = id / (KCHUNK / 4), off = (id % (KCHUNK / 4)) * 4;
            cpa16(&Ws[co * WS + off], Wl + (size_t)co * KTOT + kp0 + off);
        }
        cpa_commit();
    };

    float acc[8][4];
#pragma unroll
    for (int nt = 0; nt < 8; nt++)
#pragma unroll
        for (int r = 0; r < 4; r++) acc[nt][r] = 0.0f;

    load_stage(0, kbeg);
    for (int ch = 0; ch < NCHUNK; ch++) {
        cpa_wait_all();
        __syncthreads();
        if (STAGES == 2 && ch + 1 < NCHUNK)
            load_stage((ch + 1) & 1, kbeg + (ch + 1) * KCHUNK);

        const int st = (STAGES == 2) ? (ch & 1) : 0;
        const uint32_t* As = Asm + st * KCHUNK * AS;
        const uint32_t* Ws = Wsm + st * COUT_BLK * WS;

#pragma unroll
        for (int kk = 0; kk < KCHUNK; kk += 8) {   // 8 kp words = k16 step
            uint32_t a0 = Ws[(cot * 16 + qr) * WS + kk + qc];
            uint32_t a1 = Ws[(cot * 16 + qr + 8) * WS + kk + qc];
            uint32_t a2 = Ws[(cot * 16 + qr) * WS + kk + qc + 4];
            uint32_t a3 = Ws[(cot * 16 + qr + 8) * WS + kk + qc + 4];
#pragma unroll
            for (int p = 0; p < 4; p++) {
                int ab = bg * 64 + p * 16 + 2 * qr;
                uint2 v0 = *(const uint2*)&As[(kk + qc) * AS + ab];
                uint2 v1 = *(const uint2*)&As[(kk + qc + 4) * AS + ab];
                mma_bf16(acc[p * 2 + 0], a0, a1, a2, a3, v0.x, v1.x);
                mma_bf16(acc[p * 2 + 1], a0, a1, a2, a3, v0.y, v1.y);
            }
        }
        if (STAGES == 1) break;
    }

    // Epilogue: stage fp32 D to smem, then coalesced global writes.
    __syncthreads();
    constexpr int DS = BB + 8;
    float* Dsm = (float*)dsm;
#pragma unroll
    for (int p = 0; p < 4; p++) {
        int base = bg * 64 + p * 16 + 4 * qc;
        int row0 = cot * 16 + qr;
        *(float4*)&Dsm[row0 * DS + base] =
            make_float4(acc[2 * p][0], acc[2 * p + 1][0], acc[2 * p][1], acc[2 * p + 1][1]);
        *(float4*)&Dsm[(row0 + 8) * DS + base] =
            make_float4(acc[2 * p][2], acc[2 * p + 1][2], acc[2 * p][3], acc[2 * p + 1][3]);
    }
    __syncthreads();

    if (PARTIAL) {
        float* ob = (float*)outp + (size_t)kz * KZSTRIDE;
        for (int idx = t; idx < COUT_BLK * BB; idx += 256) {
            int co = idx / BB, bl = idx - co * BB;
            ob[((size_t)loc * COUT + cz + co) * B + b0 + bl] = Dsm[co * DS + bl];
        }
    } else {
        uint32_t* ob = (uint32_t*)outp;
        for (int idx = t; idx < (COUT_BLK / 2) * BB; idx += 256) {
            int cop = idx / BB, bl = idx - cop * BB;
            float d0 = tanhap(Dsm[(2 * cop) * DS + bl] +
                              bias[(size_t)loc * COUT + cz + 2 * cop]);
            float d1 = tanhap(Dsm[(2 * cop + 1) * DS + bl] +
                              bias[(size_t)loc * COUT + cz + 2 * cop + 1]);
            ob[((size_t)loc * (COUT / 2) + (cz >> 1) + cop) * B + b0 + bl] =
                packbf(d0, d1);
        }
    }
}

// L0: KTOT=32 kp (K'=64 padded), 1 chunk, BB=256, COUT_BLK=32.
__global__ void __launch_bounds__(256) k_l0(const float* __restrict__ b) {
    lc_mma_body<0, 20, 32, 32, 32, 256, 1, false, 0, 32, 1>(g_P0, g_W0c, b, g_H0);
}
// L1: KTOT=64 kp, KCHUNK=32, 2 chunks, 2-stage, BB=128, COUT_BLK=64.
__global__ void __launch_bounds__(256) k_l1(const float* __restrict__ b) {
    lc_mma_body<1, 10, 64, 64, 32, 128, 1, false, 0, 64, 2>(g_H0, g_W1c, b, g_H1);
}
// L2: KTOT=800 kp, split-K=4 (200 kp), KCHUNK=40, 5 chunks, 2-stage. Partials.
__global__ void __launch_bounds__(256) k_l2(const float* __restrict__ b) {
    lc_mma_body<2, 2, 128, 64, 40, 128, 4, true, 4LL * 128 * 4096, 800, 2>(
        g_H1, g_W2c, b, g_PART);
}

// ---------------------------------------------------------------------------
// Classifier + softmax with l2 split-K combine FUSED (bias + tanh inline).
// 128 blocks x 256 threads: 32 batches x 8 f-groups.
// flatten f = c*4 + loc2; partial row = loc2*128 + c = (f&3)*128 + (f>>2).
// ---------------------------------------------------------------------------
__global__ void __launch_bounds__(256) classifier_k(const float* __restrict__ info,
                                                    const float* __restrict__ Wc,
                                                    const float* __restrict__ bc,
                                                    const float* __restrict__ B2,
                                                    float* __restrict__ out) {
    constexpr int ST = 4 * 128 * 4096;
    __shared__ float wsm[1030];
    __shared__ float bsm[512];
    __shared__ float red[8][32][2];
    for (int e = threadIdx.x; e < 1028; e += 256) wsm[e] = Wc[e];
    if (threadIdx.x < 2) wsm[1028 + threadIdx.x] = bc[threadIdx.x];
    for (int e = threadIdx.x; e < 512; e += 256) bsm[e] = B2[e];
    __syncthreads();

    const int fg = threadIdx.x >> 5, lane = threadIdx.x & 31;
    const int b = blockIdx.x * 32 + lane;
    float l0 = 0.f, l1 = 0.f;
#pragma unroll 4
    for (int ff = 0; ff < 64; ff++) {
        int f = fg * 64 + ff;
        int row = (f & 3) * 128 + (f >> 2);
        size_t base = (size_t)row * 4096 + b;
        float s = bsm[row] + g_PART[base] + g_PART[base + ST]
                + g_PART[base + 2 * ST] + g_PART[base + 3 * ST];
        float hv = tanhap(s);
        l0 += hv * wsm[f * 2];
        l1 += hv * wsm[f * 2 + 1];
    }
    red[fg][lane][0] = l0;
    red[fg][lane][1] = l1;
    __syncthreads();

    if (threadIdx.x < 32) {
        int bb = blockIdx.x * 32 + threadIdx.x;
        float s0 = wsm[1028], s1 = wsm[1029];
#pragma unroll
        for (int g = 0; g < 8; g++) { s0 += red[g][threadIdx.x][0]; s1 += red[g][threadIdx.x][1]; }
        float i0 = info[2 * bb], i1 = info[2 * bb + 1];
        s0 += i0 * wsm[512 * 2]     + i1 * wsm[513 * 2];
        s1 += i0 * wsm[512 * 2 + 1] + i1 * wsm[513 * 2 + 1];
        float m = fmaxf(s0, s1);
        float e0 = __expf(s0 - m), e1 = __expf(s1 - m);
        float inv = 1.0f / (e0 + e1);
        ((float2*)out)[bb] = make_float2(e0 * inv, e1 * inv);
    }
}

extern "C" void kernel_launch(void* const* d_in, const int* in_sizes, int n_in,
                              void* d_out, int out_size) {
    const float* x    = (const float*)d_in[0];
    const float* info = (const float*)d_in[1];
    const float* W0   = (const float*)d_in[2];
    const float* B0   = (const float*)d_in[3];
    const float* W1   = (const float*)d_in[4];
    const float* B1   = (const float*)d_in[5];
    const float* W2   = (const float*)d_in[6];
    const float* B2   = (const float*)d_in[7];
    const float* Wc   = (const float*)d_in[8];
    const float* bc   = (const float*)d_in[9];
    float* out = (float*)d_out;

    // Dynamic smem: STAGES*(KCHUNK*AS + COUT_BLK*WS) words (4B each)
    const int s_l0 = (32 * 264 + 32 * 36) * 4;              // 38400
    const int s_l1 = 2 * (32 * 136 + 64 * 36) * 4;          // 53248
    const int s_l2 = 2 * (40 * 136 + 64 * 44) * 4;          // 66048
    cudaFuncSetAttribute(k_l0, cudaFuncAttributeMaxDynamicSharedMemorySize, s_l0);
    cudaFuncSetAttribute(k_l1, cudaFuncAttributeMaxDynamicSharedMemorySize, s_l1);
    cudaFuncSetAttribute(k_l2, cudaFuncAttributeMaxDynamicSharedMemorySize, s_l2);

    wconv0_k<<<(400 * 32 * 32 + 255) / 256, 256>>>(W0);
    wconv1_k<<<(100 * 64 * 64 + 255) / 256, 256>>>(W1);
    wconv2_k<<<(4 * 128 * 800 + 255) / 256, 256>>>(W2);
    im2col_k<<<dim3(120, 128), 256>>>(x);
    k_l0<<<dim3(400, 16, 1), 256, s_l0>>>(B0);        // 6400 CTAs
    k_l1<<<dim3(100, 32, 1), 256, s_l1>>>(B1);        // 3200 CTAs
    k_l2<<<dim3(4, 32, 8), 256, s_l2>>>(B2);          // 1024 CTAs (2 co x 4 kz)
    classifier_k<<<128, 256>>>(info, Wc, bc, B2, out);
}